// round 15
// baseline (speedup 1.0000x reference)
#include <cuda_runtime.h>
#include <cuda_bf16.h>
#include <cuda_fp16.h>
#include <cstdint>

// Problem constants (fixed by the reference)
#define NN 100000
#define EE 1600000
#define FF 128          // in_size == out_size
#define HH 4            // heads
#define DD 32           // per-head dim
#define LL 3            // layers
#define NEG_SLOPE 0.2f
#define GTILES ((NN + 127) / 128)

// smem padded strides
#define SA_STRIDE 136   // halves (272B = 17*16B -> conflict-free ldmatrix)
#define SC_STRIDE 133   // floats (conflict-free staged reads)

// ---------------- device scratch (no allocations allowed) ----------------
__device__ __half g_fth[(size_t)NN * FF]; // projected features (fp16 message table)
__device__ __half g_wh[(size_t)LL * FF * FF]; // fp16 W images [l][k][n]
__device__ float g_xa[(size_t)NN * FF];   // layer ping
__device__ float g_xb[(size_t)NN * FF];   // layer pong
__device__ float g_el[(size_t)NN * HH];
__device__ float g_er[(size_t)NN * HH];
__device__ int   g_deg[NN];
__device__ int   g_fill[NN];
__device__ int   g_rowptr[NN + 1];
__device__ int   g_t[NN];
__device__ int   g_bsum[256];
__device__ int2  g_cse[EE];    // (src node id, original edge id) per CSR slot

__device__ __forceinline__ uint32_t smem_u32(const void* p) {
    uint32_t a;
    asm("{ .reg .u64 t; cvta.to.shared.u64 t, %1; cvt.u32.u64 %0, t; }"
        : "=r"(a) : "l"(p));
    return a;
}

#define LDSM4(r0, r1, r2, r3, addr) \
    asm volatile("ldmatrix.sync.aligned.m8n8.x4.shared.b16 {%0,%1,%2,%3}, [%4];" \
        : "=r"(r0), "=r"(r1), "=r"(r2), "=r"(r3) : "r"(addr))
#define LDSM4T(r0, r1, r2, r3, addr) \
    asm volatile("ldmatrix.sync.aligned.m8n8.x4.trans.shared.b16 {%0,%1,%2,%3}, [%4];" \
        : "=r"(r0), "=r"(r1), "=r"(r2), "=r"(r3) : "r"(addr))
#define MMA16816(c, a, b) \
    asm volatile("mma.sync.aligned.m16n8k16.row.col.f32.f16.f16.f32 " \
        "{%0,%1,%2,%3}, {%4,%5,%6,%7}, {%8,%9}, {%0,%1,%2,%3};" \
        : "+f"((c)[0]), "+f"((c)[1]), "+f"((c)[2]), "+f"((c)[3]) \
        : "r"((a)[0]), "r"((a)[1]), "r"((a)[2]), "r"((a)[3]), \
          "r"((b)[0]), "r"((b)[1]))

// ---------------- W fp16 image prep + deg/fill zero (merged) ----------------
__global__ void k_prep(const float* __restrict__ Ws) {
    int i = blockIdx.x * blockDim.x + threadIdx.x;
    if (i < LL * FF * FF) g_wh[i] = __float2half(Ws[i]);
    if (i < NN) { g_deg[i] = 0; g_fill[i] = 0; }
}

// ---------------- CSR build ----------------
__global__ void k_hist(const int* __restrict__ dst) {
    int e = blockIdx.x * blockDim.x + threadIdx.x;
    if (e < EE) atomicAdd(&g_deg[dst[e]], 1);
}

__global__ void k_scan1() {
    __shared__ int s[512];
    int tid = threadIdx.x;
    int i = blockIdx.x * 512 + tid;
    int v = (i < NN) ? g_deg[i] : 0;
    s[tid] = v;
    __syncthreads();
    for (int off = 1; off < 512; off <<= 1) {
        int t = (tid >= off) ? s[tid - off] : 0;
        __syncthreads();
        s[tid] += t;
        __syncthreads();
    }
    if (i < NN) g_t[i] = s[tid];
    if (tid == 511) g_bsum[blockIdx.x] = s[511];
}

__global__ void k_scan2(int nb) {
    __shared__ int s[256];
    int tid = threadIdx.x;
    int v = (tid < nb) ? g_bsum[tid] : 0;
    s[tid] = v;
    __syncthreads();
    for (int off = 1; off < 256; off <<= 1) {
        int t = (tid >= off) ? s[tid - off] : 0;
        __syncthreads();
        s[tid] += t;
        __syncthreads();
    }
    if (tid < nb) g_bsum[tid] = s[tid] - v;  // exclusive
}

__global__ void k_scan3() {
    int i = blockIdx.x * blockDim.x + threadIdx.x;
    if (i < NN) {
        g_rowptr[i + 1] = g_t[i] + g_bsum[i >> 9];
        if (i == 0) g_rowptr[0] = 0;
    }
}

__global__ void k_scatter(const int* __restrict__ src, const int* __restrict__ dst) {
    int e = blockIdx.x * blockDim.x + threadIdx.x;
    if (e < EE) {
        int d = dst[e];
        int p = g_rowptr[d] + atomicAdd(&g_fill[d], 1);
        g_cse[p] = make_int2(src[e], e);
    }
}

// ---------------- HMMA projection GEMM + attention dots ---------------------
// (unchanged — measured 46.5us, tensor pipe active)
__global__ void __launch_bounds__(256, 2)
k_gemm(const float* __restrict__ x, const __half* __restrict__ wimg,
       const float* __restrict__ al, const float* __restrict__ ar) {
    extern __shared__ __align__(16) char smem[];
    float*  s_al = (float*)smem;
    float*  s_ar = (float*)(smem + 512);
    __half* sA   = (__half*)(smem + 1024);
    __half* sB   = (__half*)(smem + 1024 + 34816);
    float*  sC   = (float*)(smem + 1024);

    int tid = threadIdx.x, wid = tid >> 5, lane = tid & 31;
    int tile = blockIdx.x;
    int row2 = tid >> 1, seg = tid & 1;

    if (tid < 128) { s_al[tid] = al[tid]; s_ar[tid] = ar[tid]; }

    {
        int m = tile * 128 + row2;
        uint32_t hv[32];
        if (m < NN) {
            const float4* xr = (const float4*)(x + (size_t)m * FF + seg * 64);
#pragma unroll
            for (int i = 0; i < 16; i++) {
                float4 v = xr[i];
                __half2 h0 = __floats2half2_rn(v.x, v.y);
                __half2 h1 = __floats2half2_rn(v.z, v.w);
                hv[2 * i]     = *(uint32_t*)&h0;
                hv[2 * i + 1] = *(uint32_t*)&h1;
            }
        } else {
#pragma unroll
            for (int i = 0; i < 32; i++) hv[i] = 0;
        }
        uint4* dp = (uint4*)(sA + row2 * SA_STRIDE + seg * 64);
#pragma unroll
        for (int i = 0; i < 8; i++)
            dp[i] = make_uint4(hv[4 * i], hv[4 * i + 1], hv[4 * i + 2], hv[4 * i + 3]);
    }
    {
        const uint4* ws = (const uint4*)(wimg + row2 * FF + seg * 64);
        uint4* dp = (uint4*)(sB + row2 * SA_STRIDE + seg * 64);
#pragma unroll
        for (int i = 0; i < 8; i++) dp[i] = ws[i];
    }
    __syncthreads();

    int wq = wid >> 1, wr = wid & 1;
    int R0 = wq * 32, C0 = wr * 64;
    int q = lane >> 3, r = lane & 7;

    uint32_t aA[2], aB[4];
#pragma unroll
    for (int i = 0; i < 2; i++) {
        int rr = R0 + 16 * i + (q & 1) * 8 + r;
        int cc = (q >> 1) * 8;
        aA[i] = smem_u32(sA + rr * SA_STRIDE + cc);
    }
#pragma unroll
    for (int p = 0; p < 4; p++) {
        int rr = (q & 1) * 8 + r;
        int cc = C0 + p * 16 + (q >> 1) * 8;
        aB[p] = smem_u32(sB + rr * SA_STRIDE + cc);
    }

    float acc[2][8][4];
#pragma unroll
    for (int i = 0; i < 2; i++)
#pragma unroll
        for (int nb = 0; nb < 8; nb++)
#pragma unroll
            for (int c = 0; c < 4; c++) acc[i][nb][c] = 0.f;

#pragma unroll
    for (int s = 0; s < 8; s++) {
        uint32_t af[2][4];
        LDSM4(af[0][0], af[0][1], af[0][2], af[0][3], aA[0]);
        LDSM4(af[1][0], af[1][1], af[1][2], af[1][3], aA[1]);
        uint32_t bf[8][2];
#pragma unroll
        for (int p = 0; p < 4; p++) {
            uint32_t t0, t1, t2, t3;
            LDSM4T(t0, t1, t2, t3, aB[p]);
            bf[2 * p][0] = t0;     bf[2 * p][1] = t1;
            bf[2 * p + 1][0] = t2; bf[2 * p + 1][1] = t3;
        }
#pragma unroll
        for (int i = 0; i < 2; i++)
#pragma unroll
            for (int nb = 0; nb < 8; nb++)
                MMA16816(acc[i][nb], af[i], bf[nb]);
        aA[0] += 32; aA[1] += 32;
        aB[0] += 16 * SA_STRIDE * 2; aB[1] += 16 * SA_STRIDE * 2;
        aB[2] += 16 * SA_STRIDE * 2; aB[3] += 16 * SA_STRIDE * 2;
    }
    __syncthreads();

    int gid = lane >> 2, tig = lane & 3;
#pragma unroll
    for (int i = 0; i < 2; i++)
#pragma unroll
        for (int nb = 0; nb < 8; nb++) {
            int rr = R0 + 16 * i + gid;
            int cc = C0 + nb * 8 + tig * 2;
            sC[rr * SC_STRIDE + cc]           = acc[i][nb][0];
            sC[rr * SC_STRIDE + cc + 1]       = acc[i][nb][1];
            sC[(rr + 8) * SC_STRIDE + cc]     = acc[i][nb][2];
            sC[(rr + 8) * SC_STRIDE + cc + 1] = acc[i][nb][3];
        }
    __syncthreads();

    {
        int rrow = tid & 127, hf = tid >> 7;
        int m = tile * 128 + rrow;
        if (m < NN) {
            const float* cr = sC + rrow * SC_STRIDE + hf * 64;
            uint32_t pk[32];
            float e0 = 0.f, e1 = 0.f, rg0 = 0.f, rg1 = 0.f;
#pragma unroll
            for (int j = 0; j < 32; j++) {
                float v0 = cr[2 * j], v1 = cr[2 * j + 1];
                __half2 p = __floats2half2_rn(v0, v1);
                pk[j] = *(uint32_t*)&p;
            }
#pragma unroll
            for (int j = 0; j < 32; j++) {
                e0  += cr[j]      * s_al[hf * 64 + j];
                rg0 += cr[j]      * s_ar[hf * 64 + j];
                e1  += cr[32 + j] * s_al[hf * 64 + 32 + j];
                rg1 += cr[32 + j] * s_ar[hf * 64 + 32 + j];
            }
            uint4* dst = (uint4*)(g_fth + (size_t)m * FF + hf * 64);
#pragma unroll
            for (int j = 0; j < 8; j++)
                dst[j] = make_uint4(pk[4 * j], pk[4 * j + 1], pk[4 * j + 2], pk[4 * j + 3]);
            g_el[m * HH + hf * 2]     = e0;
            g_er[m * HH + hf * 2]     = rg0;
            g_el[m * HH + hf * 2 + 1] = e1;
            g_er[m * HH + hf * 2 + 1] = rg1;
        }
    }
}

// ---------------- fused edge softmax + aggregation + residual + ELU ---------
// TWO warps per node: warp-half hw owns heads {2hw, 2hw+1} and cols [64hw,+64).
__device__ __forceinline__ float lrelu(float v) { return v > 0.f ? v : NEG_SLOPE * v; }
__device__ __forceinline__ float2 h2f(unsigned int u) {
    __half2 h = *reinterpret_cast<__half2*>(&u);
    return __half22float2(h);
}

#define ACC4(V, U) do { \
    float2 _q; \
    _q = h2f((V).x); acc[0] += (U) * _q.x; acc[1] += (U) * _q.y; \
    _q = h2f((V).y); acc[2] += (U) * _q.x; acc[3] += (U) * _q.y; \
} while (0)

// Dual-edge gather over cnt (<=32) edges staged in s_row/a_row (2 heads).
// Lanes 0-15 even edges, 16-31 odd; each lane covers 4 cols via one uint2.
__device__ __forceinline__ void gather_chunk2(
    const int* __restrict__ s_row, const float* __restrict__ a_row,
    int cnt, int half, int hd, int c0, float* acc)
{
    int j = 0;
    for (; j + 8 <= cnt; j += 8) {
        int e0 = j + half, e1 = j + 2 + half, e2 = j + 4 + half, e3 = j + 6 + half;
        int s0 = s_row[e0], s1 = s_row[e1], s2 = s_row[e2], s3 = s_row[e3];
        float u0 = a_row[e0 * 2 + hd], u1 = a_row[e1 * 2 + hd];
        float u2 = a_row[e2 * 2 + hd], u3 = a_row[e3 * 2 + hd];
        uint2 v0 = *(const uint2*)(g_fth + (size_t)s0 * FF + c0);
        uint2 v1 = *(const uint2*)(g_fth + (size_t)s1 * FF + c0);
        uint2 v2 = *(const uint2*)(g_fth + (size_t)s2 * FF + c0);
        uint2 v3 = *(const uint2*)(g_fth + (size_t)s3 * FF + c0);
        ACC4(v0, u0); ACC4(v1, u1); ACC4(v2, u2); ACC4(v3, u3);
    }
    for (; j + 2 <= cnt; j += 2) {
        int e = j + half;
        int s = s_row[e];
        float u = a_row[e * 2 + hd];
        uint2 v = *(const uint2*)(g_fth + (size_t)s * FF + c0);
        ACC4(v, u);
    }
    if (j < cnt) {
        int s = s_row[j];
        float u = half ? 0.f : a_row[j * 2 + hd];
        uint2 v = *(const uint2*)(g_fth + (size_t)s * FF + c0);
        ACC4(v, u);
    }
}

__global__ void __launch_bounds__(256)
k_edge(const float* __restrict__ xin, const float* __restrict__ bias,
       float* __restrict__ xout, float* __restrict__ aout) {
    __shared__ float a_sm[8][64];    // per warp: 32 edges x 2 heads
    __shared__ int   s_sm[8][32];    // per warp: src ids of current chunk
    int tid = threadIdx.x, w = tid >> 5, lane = tid & 31;
    int n  = blockIdx.x * 4 + (w >> 1);
    int hw = w & 1;                  // which head-pair / col-half this warp owns
    if (n >= NN) return;

    int base = g_rowptr[n];
    int deg  = g_rowptr[n + 1] - base;
    float2 er2 = *(const float2*)(g_er + (size_t)n * HH + hw * 2);

    int half = lane >> 4;            // edge parity in gather
    int sub  = lane & 15;
    int hd   = sub >> 3;             // head within this warp's pair
    int c0   = hw * 64 + sub * 4;    // 4-col slice (elements)
    float acc[4];
#pragma unroll
    for (int k = 0; k < 4; k++) acc[k] = 0.f;

    if (deg <= 32) {
        // ===== fast path: one lane per edge for softmax (2 heads) =====
        bool act = lane < deg;
        int2 se = make_int2(0, 0);
        float e0 = -1e30f, e1 = -1e30f;
        if (act) {
            se = g_cse[base + lane];
            float2 el2 = *(const float2*)(g_el + (size_t)se.x * HH + hw * 2);
            e0 = lrelu(el2.x + er2.x);
            e1 = lrelu(el2.y + er2.y);
        }
        float m0 = e0, m1 = e1;
#pragma unroll
        for (int o = 16; o; o >>= 1) {
            m0 = fmaxf(m0, __shfl_xor_sync(0xffffffffu, m0, o));
            m1 = fmaxf(m1, __shfl_xor_sync(0xffffffffu, m1, o));
        }
        float x0 = act ? __expf(e0 - m0) : 0.f;
        float x1 = act ? __expf(e1 - m1) : 0.f;
        float d0 = x0, d1 = x1;
#pragma unroll
        for (int o = 16; o; o >>= 1) {
            d0 += __shfl_xor_sync(0xffffffffu, d0, o);
            d1 += __shfl_xor_sync(0xffffffffu, d1, o);
        }
        float a0 = x0 / fmaxf(d0, 1e-9f);
        float a1 = x1 / fmaxf(d1, 1e-9f);
        if (act) {
            *(float2*)(&a_sm[w][lane * 2]) = make_float2(a0, a1);
            s_sm[w][lane] = se.x;
            if (aout)
                *(float2*)(aout + (size_t)se.y * HH + hw * 2) = make_float2(a0, a1);
        }
        __syncwarp();
        gather_chunk2(s_sm[w], a_sm[w], deg, half, hd, c0, acc);
        __syncwarp();
    } else {
        // ===== general path (deg > 32): 3-phase, 2 heads =====
        float m0 = -1e30f, m1 = -1e30f;
        float ec0[2], ec1[2];
        for (int i = lane, r = 0; i < deg; i += 32, ++r) {
            int s = g_cse[base + i].x;
            float2 el2 = *(const float2*)(g_el + (size_t)s * HH + hw * 2);
            float e0 = lrelu(el2.x + er2.x);
            float e1 = lrelu(el2.y + er2.y);
            if (r < 2) { ec0[r] = e0; ec1[r] = e1; }
            m0 = fmaxf(m0, e0); m1 = fmaxf(m1, e1);
        }
#pragma unroll
        for (int o = 16; o; o >>= 1) {
            m0 = fmaxf(m0, __shfl_xor_sync(0xffffffffu, m0, o));
            m1 = fmaxf(m1, __shfl_xor_sync(0xffffffffu, m1, o));
        }
        float d0 = 0.f, d1 = 0.f;
        for (int i = lane, r = 0; i < deg; i += 32, ++r) {
            float e0, e1;
            if (r < 2) { e0 = ec0[r]; e1 = ec1[r]; }
            else {
                int s = g_cse[base + i].x;
                float2 el2 = *(const float2*)(g_el + (size_t)s * HH + hw * 2);
                e0 = lrelu(el2.x + er2.x); e1 = lrelu(el2.y + er2.y);
            }
            float x0 = __expf(e0 - m0), x1 = __expf(e1 - m1);
            if (r < 2) { ec0[r] = x0; ec1[r] = x1; }
            d0 += x0; d1 += x1;
        }
#pragma unroll
        for (int o = 16; o; o >>= 1) {
            d0 += __shfl_xor_sync(0xffffffffu, d0, o);
            d1 += __shfl_xor_sync(0xffffffffu, d1, o);
        }
        float i0 = 1.f / fmaxf(d0, 1e-9f), i1 = 1.f / fmaxf(d1, 1e-9f);

        for (int j0 = 0; j0 < deg; j0 += 32) {
            int i = j0 + lane, r = i >> 5;
            if (i < deg) {
                int2 se = g_cse[base + i];
                float x0, x1;
                if (r < 2) { x0 = ec0[r]; x1 = ec1[r]; }
                else {
                    float2 el2 = *(const float2*)(g_el + (size_t)se.x * HH + hw * 2);
                    x0 = __expf(lrelu(el2.x + er2.x) - m0);
                    x1 = __expf(lrelu(el2.y + er2.y) - m1);
                }
                float a0 = x0 * i0, a1 = x1 * i1;
                *(float2*)(&a_sm[w][lane * 2]) = make_float2(a0, a1);
                s_sm[w][lane] = se.x;
                if (aout)
                    *(float2*)(aout + (size_t)se.y * HH + hw * 2) = make_float2(a0, a1);
            }
            __syncwarp();
            int cnt = min(32, deg - j0);
            gather_chunk2(s_sm[w], a_sm[w], cnt, half, hd, c0, acc);
            __syncwarp();
        }
    }

    // ---- merge even/odd edge partials across half-warps ----
#pragma unroll
    for (int k = 0; k < 4; k++)
        acc[k] += __shfl_xor_sync(0xffffffffu, acc[k], 16);

    // ---- epilogue: residual + bias + ELU (lanes 0-15, 4 cols each) ----
    if (lane < 16) {
        float4 xv = *(const float4*)(xin + (size_t)n * FF + c0);
        float4 bv = *(const float4*)(bias + c0);
        float r0 = acc[0] + xv.x + bv.x;
        float r1 = acc[1] + xv.y + bv.y;
        float r2 = acc[2] + xv.z + bv.z;
        float r3 = acc[3] + xv.w + bv.w;
        r0 = r0 > 0.f ? r0 : (__expf(r0) - 1.f);
        r1 = r1 > 0.f ? r1 : (__expf(r1) - 1.f);
        r2 = r2 > 0.f ? r2 : (__expf(r2) - 1.f);
        r3 = r3 > 0.f ? r3 : (__expf(r3) - 1.f);
        *(float4*)(xout + (size_t)n * FF + c0) = make_float4(r0, r1, r2, r3);
    }
}

// ---------------- launch ----------------
extern "C" void kernel_launch(void* const* d_in, const int* in_sizes, int n_in,
                              void* d_out, int out_size) {
    const float* h     = (const float*)d_in[0];
    const int*   src   = (const int*)d_in[1];
    const int*   dst   = (const int*)d_in[2];
    const float* Ws    = (const float*)d_in[3];
    const float* attnl = (const float*)d_in[4];
    const float* attnr = (const float*)d_in[5];
    const float* bias  = (const float*)d_in[6];

    float* out_x = (float*)d_out;
    float* out_a = out_x + ((size_t)out_size - (size_t)EE * HH);

    const int gemm_smem = 1024 + 2 * (128 * SA_STRIDE * 2);  // 70656B
    cudaFuncSetAttribute(k_gemm, cudaFuncAttributeMaxDynamicSharedMemorySize, gemm_smem);

    float *p_xa, *p_xb;
    __half* p_wh;
    cudaGetSymbolAddress((void**)&p_xa, g_xa);
    cudaGetSymbolAddress((void**)&p_xb, g_xb);
    cudaGetSymbolAddress((void**)&p_wh, g_wh);
    const float* lin[3]  = { h, p_xa, p_xb };
    float*       lout[3] = { p_xa, p_xb, out_x };

    // Launch order keeps layer-0 k_gemm at index 3 (the profiled slot).
    k_prep<<<(NN + 255) / 256, 256>>>(Ws);       // W fp16 + zero deg/fill
    k_hist<<<(EE + 255) / 256, 256>>>(dst);
    int nb = (NN + 511) / 512;
    k_scan1<<<nb, 512>>>();
    k_gemm<<<GTILES, 256, gemm_smem>>>(lin[0], p_wh, attnl, attnr);   // layer 0
    k_scan2<<<1, 256>>>(nb);
    k_scan3<<<(NN + 255) / 256, 256>>>();
    k_scatter<<<(EE + 255) / 256, 256>>>(src, dst);

    for (int l = 0; l < LL; ++l) {
        const float* al = attnl + (size_t)l * HH * DD;
        const float* ar = attnr + (size_t)l * HH * DD;
        const float* b  = bias  + (size_t)l * HH * DD;
        if (l > 0)
            k_gemm<<<GTILES, 256, gemm_smem>>>(lin[l], p_wh + (size_t)l * FF * FF, al, ar);
        k_edge<<<(NN + 3) / 4, 256>>>(lin[l], b, lout[l],
                                      (l == LL - 1) ? out_a : nullptr);
    }
    (void)in_sizes; (void)n_in;
}

// round 16
// speedup vs baseline: 1.2025x; 1.2025x over previous
#include <cuda_runtime.h>
#include <cuda_bf16.h>
#include <cuda_fp16.h>
#include <cstdint>

// Problem constants (fixed by the reference)
#define NN 100000
#define EE 1600000
#define FF 128          // in_size == out_size
#define HH 4            // heads
#define DD 32           // per-head dim
#define LL 3            // layers
#define NEG_SLOPE 0.2f
#define GTILES ((NN + 127) / 128)

// smem padded strides
#define SA_STRIDE 136   // halves (272B = 17*16B -> conflict-free ldmatrix)
#define SC_STRIDE 133   // floats (conflict-free staged reads)

// ---------------- device scratch (no allocations allowed) ----------------
__device__ __half g_fth[(size_t)NN * FF]; // projected features (fp16 message table)
__device__ __half g_wh[(size_t)LL * FF * FF]; // fp16 W images [l][k][n]
__device__ __half g_xha[(size_t)NN * FF]; // fp16 activation ping
__device__ __half g_xhb[(size_t)NN * FF]; // fp16 activation pong
__device__ float g_el[(size_t)NN * HH];
__device__ float g_er[(size_t)NN * HH];
__device__ int   g_deg[NN];
__device__ int   g_fill[NN];
__device__ int   g_t[NN];       // inclusive per-block scan of deg
__device__ int   g_bsum[256];   // exclusive block offsets
__device__ int2  g_cse[EE];     // (src node id, original edge id) per CSR slot

__device__ __forceinline__ uint32_t smem_u32(const void* p) {
    uint32_t a;
    asm("{ .reg .u64 t; cvta.to.shared.u64 t, %1; cvt.u32.u64 %0, t; }"
        : "=r"(a) : "l"(p));
    return a;
}
// rowptr computed inline from scan pieces (scan3 kernel removed)
__device__ __forceinline__ int rowptr_of(int i) {   // exclusive prefix at node i
    return (i > 0) ? (g_t[i - 1] + g_bsum[(i - 1) >> 9]) : 0;
}

#define LDSM4(r0, r1, r2, r3, addr) \
    asm volatile("ldmatrix.sync.aligned.m8n8.x4.shared.b16 {%0,%1,%2,%3}, [%4];" \
        : "=r"(r0), "=r"(r1), "=r"(r2), "=r"(r3) : "r"(addr))
#define LDSM4T(r0, r1, r2, r3, addr) \
    asm volatile("ldmatrix.sync.aligned.m8n8.x4.trans.shared.b16 {%0,%1,%2,%3}, [%4];" \
        : "=r"(r0), "=r"(r1), "=r"(r2), "=r"(r3) : "r"(addr))
#define MMA16816(c, a, b) \
    asm volatile("mma.sync.aligned.m16n8k16.row.col.f32.f16.f16.f32 " \
        "{%0,%1,%2,%3}, {%4,%5,%6,%7}, {%8,%9}, {%0,%1,%2,%3};" \
        : "+f"((c)[0]), "+f"((c)[1]), "+f"((c)[2]), "+f"((c)[3]) \
        : "r"((a)[0]), "r"((a)[1]), "r"((a)[2]), "r"((a)[3]), \
          "r"((b)[0]), "r"((b)[1]))

// ---------------- W fp16 image prep + deg/fill zero (merged) ----------------
__global__ void k_prep(const float* __restrict__ Ws) {
    int i = blockIdx.x * blockDim.x + threadIdx.x;
    if (i < LL * FF * FF) g_wh[i] = __float2half(Ws[i]);
    if (i < NN) { g_deg[i] = 0; g_fill[i] = 0; }
}

// ---------------- CSR build ----------------
__global__ void k_hist(const int* __restrict__ dst) {
    int e = blockIdx.x * blockDim.x + threadIdx.x;
    if (e < EE) atomicAdd(&g_deg[dst[e]], 1);
}

__global__ void k_scan1() {
    __shared__ int s[512];
    int tid = threadIdx.x;
    int i = blockIdx.x * 512 + tid;
    int v = (i < NN) ? g_deg[i] : 0;
    s[tid] = v;
    __syncthreads();
    for (int off = 1; off < 512; off <<= 1) {
        int t = (tid >= off) ? s[tid - off] : 0;
        __syncthreads();
        s[tid] += t;
        __syncthreads();
    }
    if (i < NN) g_t[i] = s[tid];
    if (tid == 511) g_bsum[blockIdx.x] = s[511];
}

__global__ void k_scan2(int nb) {
    __shared__ int s[256];
    int tid = threadIdx.x;
    int v = (tid < nb) ? g_bsum[tid] : 0;
    s[tid] = v;
    __syncthreads();
    for (int off = 1; off < 256; off <<= 1) {
        int t = (tid >= off) ? s[tid - off] : 0;
        __syncthreads();
        s[tid] += t;
        __syncthreads();
    }
    if (tid < nb) g_bsum[tid] = s[tid] - v;  // exclusive
}

__global__ void k_scatter(const int* __restrict__ src, const int* __restrict__ dst) {
    int e = blockIdx.x * blockDim.x + threadIdx.x;
    if (e < EE) {
        int d = dst[e];
        int p = rowptr_of(d) + atomicAdd(&g_fill[d], 1);
        g_cse[p] = make_int2(src[e], e);
    }
}

// ---------------- HMMA projection GEMM + attention dots ---------------------
// XH: x is fp16 (inter-layer activation) vs fp32 (layer-0 input h).
template <bool XH>
__global__ void __launch_bounds__(256, 2)
k_gemm(const void* __restrict__ xv_, const __half* __restrict__ wimg,
       const float* __restrict__ al, const float* __restrict__ ar) {
    extern __shared__ __align__(16) char smem[];
    float*  s_al = (float*)smem;
    float*  s_ar = (float*)(smem + 512);
    __half* sA   = (__half*)(smem + 1024);
    __half* sB   = (__half*)(smem + 1024 + 34816);
    float*  sC   = (float*)(smem + 1024);

    int tid = threadIdx.x, wid = tid >> 5, lane = tid & 31;
    int tile = blockIdx.x;
    int row2 = tid >> 1, seg = tid & 1;

    if (tid < 128) { s_al[tid] = al[tid]; s_ar[tid] = ar[tid]; }

    // ---- fill A ----
    {
        int m = tile * 128 + row2;
        uint4* dp = (uint4*)(sA + row2 * SA_STRIDE + seg * 64);
        if (XH) {
            if (m < NN) {
                const uint4* xr = (const uint4*)((const __half*)xv_ + (size_t)m * FF + seg * 64);
#pragma unroll
                for (int i = 0; i < 8; i++) dp[i] = xr[i];
            } else {
#pragma unroll
                for (int i = 0; i < 8; i++) dp[i] = make_uint4(0, 0, 0, 0);
            }
        } else {
            uint32_t hv[32];
            if (m < NN) {
                const float4* xr = (const float4*)((const float*)xv_ + (size_t)m * FF + seg * 64);
#pragma unroll
                for (int i = 0; i < 16; i++) {
                    float4 v = xr[i];
                    __half2 h0 = __floats2half2_rn(v.x, v.y);
                    __half2 h1 = __floats2half2_rn(v.z, v.w);
                    hv[2 * i]     = *(uint32_t*)&h0;
                    hv[2 * i + 1] = *(uint32_t*)&h1;
                }
            } else {
#pragma unroll
                for (int i = 0; i < 32; i++) hv[i] = 0;
            }
#pragma unroll
            for (int i = 0; i < 8; i++)
                dp[i] = make_uint4(hv[4 * i], hv[4 * i + 1], hv[4 * i + 2], hv[4 * i + 3]);
        }
    }
    // ---- fill B ----
    {
        const uint4* ws = (const uint4*)(wimg + row2 * FF + seg * 64);
        uint4* dp = (uint4*)(sB + row2 * SA_STRIDE + seg * 64);
#pragma unroll
        for (int i = 0; i < 8; i++) dp[i] = ws[i];
    }
    __syncthreads();

    int wq = wid >> 1, wr = wid & 1;
    int R0 = wq * 32, C0 = wr * 64;
    int q = lane >> 3, r = lane & 7;

    uint32_t aA[2], aB[4];
#pragma unroll
    for (int i = 0; i < 2; i++) {
        int rr = R0 + 16 * i + (q & 1) * 8 + r;
        int cc = (q >> 1) * 8;
        aA[i] = smem_u32(sA + rr * SA_STRIDE + cc);
    }
#pragma unroll
    for (int p = 0; p < 4; p++) {
        int rr = (q & 1) * 8 + r;
        int cc = C0 + p * 16 + (q >> 1) * 8;
        aB[p] = smem_u32(sB + rr * SA_STRIDE + cc);
    }

    float acc[2][8][4];
#pragma unroll
    for (int i = 0; i < 2; i++)
#pragma unroll
        for (int nb = 0; nb < 8; nb++)
#pragma unroll
            for (int c = 0; c < 4; c++) acc[i][nb][c] = 0.f;

#pragma unroll
    for (int s = 0; s < 8; s++) {
        uint32_t af[2][4];
        LDSM4(af[0][0], af[0][1], af[0][2], af[0][3], aA[0]);
        LDSM4(af[1][0], af[1][1], af[1][2], af[1][3], aA[1]);
        uint32_t bf[8][2];
#pragma unroll
        for (int p = 0; p < 4; p++) {
            uint32_t t0, t1, t2, t3;
            LDSM4T(t0, t1, t2, t3, aB[p]);
            bf[2 * p][0] = t0;     bf[2 * p][1] = t1;
            bf[2 * p + 1][0] = t2; bf[2 * p + 1][1] = t3;
        }
#pragma unroll
        for (int i = 0; i < 2; i++)
#pragma unroll
            for (int nb = 0; nb < 8; nb++)
                MMA16816(acc[i][nb], af[i], bf[nb]);
        aA[0] += 32; aA[1] += 32;
        aB[0] += 16 * SA_STRIDE * 2; aB[1] += 16 * SA_STRIDE * 2;
        aB[2] += 16 * SA_STRIDE * 2; aB[3] += 16 * SA_STRIDE * 2;
    }
    __syncthreads();

    int gid = lane >> 2, tig = lane & 3;
#pragma unroll
    for (int i = 0; i < 2; i++)
#pragma unroll
        for (int nb = 0; nb < 8; nb++) {
            int rr = R0 + 16 * i + gid;
            int cc = C0 + nb * 8 + tig * 2;
            sC[rr * SC_STRIDE + cc]           = acc[i][nb][0];
            sC[rr * SC_STRIDE + cc + 1]       = acc[i][nb][1];
            sC[(rr + 8) * SC_STRIDE + cc]     = acc[i][nb][2];
            sC[(rr + 8) * SC_STRIDE + cc + 1] = acc[i][nb][3];
        }
    __syncthreads();

    {
        int rrow = tid & 127, hf = tid >> 7;
        int m = tile * 128 + rrow;
        if (m < NN) {
            const float* cr = sC + rrow * SC_STRIDE + hf * 64;
            uint32_t pk[32];
            float e0 = 0.f, e1 = 0.f, rg0 = 0.f, rg1 = 0.f;
#pragma unroll
            for (int j = 0; j < 32; j++) {
                float v0 = cr[2 * j], v1 = cr[2 * j + 1];
                __half2 p = __floats2half2_rn(v0, v1);
                pk[j] = *(uint32_t*)&p;
            }
#pragma unroll
            for (int j = 0; j < 32; j++) {
                e0  += cr[j]      * s_al[hf * 64 + j];
                rg0 += cr[j]      * s_ar[hf * 64 + j];
                e1  += cr[32 + j] * s_al[hf * 64 + 32 + j];
                rg1 += cr[32 + j] * s_ar[hf * 64 + 32 + j];
            }
            uint4* dst = (uint4*)(g_fth + (size_t)m * FF + hf * 64);
#pragma unroll
            for (int j = 0; j < 8; j++)
                dst[j] = make_uint4(pk[4 * j], pk[4 * j + 1], pk[4 * j + 2], pk[4 * j + 3]);
            g_el[m * HH + hf * 2]     = e0;
            g_er[m * HH + hf * 2]     = rg0;
            g_el[m * HH + hf * 2 + 1] = e1;
            g_er[m * HH + hf * 2 + 1] = rg1;
        }
    }
}

// ---------------- fused edge softmax + aggregation + residual + ELU ----------------
__device__ __forceinline__ float lrelu(float v) { return v > 0.f ? v : NEG_SLOPE * v; }
__device__ __forceinline__ float2 h2f(unsigned int u) {
    __half2 h = *reinterpret_cast<__half2*>(&u);
    return __half22float2(h);
}

#define ACC8(V, U) do { \
    float2 _q; \
    _q = h2f((V).x); acc[0] += (U) * _q.x; acc[1] += (U) * _q.y; \
    _q = h2f((V).y); acc[2] += (U) * _q.x; acc[3] += (U) * _q.y; \
    _q = h2f((V).z); acc[4] += (U) * _q.x; acc[5] += (U) * _q.y; \
    _q = h2f((V).w); acc[6] += (U) * _q.x; acc[7] += (U) * _q.y; \
} while (0)

// Dual-row gather over a chunk of cnt (<=32) edges staged in s_row/a_row.
// Lanes 0-15 take even-parity edges, 16-31 odd; each lane covers 8 cols at c0.
__device__ __forceinline__ void gather_chunk(
    const int* __restrict__ s_row, const float* __restrict__ a_row,
    int cnt, int half, int hd, int c0, float* acc)
{
    int j = 0;
    for (; j + 8 <= cnt; j += 8) {
        int e0 = j + half, e1 = j + 2 + half, e2 = j + 4 + half, e3 = j + 6 + half;
        int s0 = s_row[e0], s1 = s_row[e1], s2 = s_row[e2], s3 = s_row[e3];
        float u0 = a_row[e0 * 4 + hd], u1 = a_row[e1 * 4 + hd];
        float u2 = a_row[e2 * 4 + hd], u3 = a_row[e3 * 4 + hd];
        uint4 v0 = *(const uint4*)(g_fth + (size_t)s0 * FF + c0);
        uint4 v1 = *(const uint4*)(g_fth + (size_t)s1 * FF + c0);
        uint4 v2 = *(const uint4*)(g_fth + (size_t)s2 * FF + c0);
        uint4 v3 = *(const uint4*)(g_fth + (size_t)s3 * FF + c0);
        ACC8(v0, u0); ACC8(v1, u1); ACC8(v2, u2); ACC8(v3, u3);
    }
    for (; j + 2 <= cnt; j += 2) {
        int e = j + half;
        int s = s_row[e];
        float u = a_row[e * 4 + hd];
        uint4 v = *(const uint4*)(g_fth + (size_t)s * FF + c0);
        ACC8(v, u);
    }
    if (j < cnt) {
        int s = s_row[j];
        float u = half ? 0.f : a_row[j * 4 + hd];
        uint4 v = *(const uint4*)(g_fth + (size_t)s * FF + c0);
        ACC8(v, u);
    }
}

template <bool XIN_H, bool XOUT_H>
__global__ void __launch_bounds__(256)
k_edge(const void* __restrict__ xin_, const float* __restrict__ bias,
       void* __restrict__ xout_, float* __restrict__ aout) {
    __shared__ float a_sm[8][128];
    __shared__ int   s_sm[8][32];
    int w = threadIdx.x >> 5, lane = threadIdx.x & 31;
    int n = blockIdx.x * 8 + w;
    if (n >= NN) return;

    int base = rowptr_of(n);
    int deg  = (g_t[n] + g_bsum[n >> 9]) - base;
    float4 er4 = *(const float4*)(g_er + (size_t)n * HH);

    int half = lane >> 4;            // edge parity this lane serves
    int hd   = (lane & 15) >> 2;     // head of my 8-col slice
    int c0   = (lane & 15) * 8;      // col offset (elements)
    float acc[8];
#pragma unroll
    for (int k = 0; k < 8; k++) acc[k] = 0.f;

    if (deg <= 32) {
        // ===== fast path: one lane per edge for softmax =====
        bool act = lane < deg;
        int2 se = make_int2(0, 0);
        float e0 = -1e30f, e1 = -1e30f, e2 = -1e30f, e3 = -1e30f;
        if (act) {
            se = g_cse[base + lane];
            float4 el4 = *(const float4*)(g_el + (size_t)se.x * HH);
            e0 = lrelu(el4.x + er4.x);
            e1 = lrelu(el4.y + er4.y);
            e2 = lrelu(el4.z + er4.z);
            e3 = lrelu(el4.w + er4.w);
        }
        float m0 = e0, m1 = e1, m2 = e2, m3 = e3;
#pragma unroll
        for (int o = 16; o; o >>= 1) {
            m0 = fmaxf(m0, __shfl_xor_sync(0xffffffffu, m0, o));
            m1 = fmaxf(m1, __shfl_xor_sync(0xffffffffu, m1, o));
            m2 = fmaxf(m2, __shfl_xor_sync(0xffffffffu, m2, o));
            m3 = fmaxf(m3, __shfl_xor_sync(0xffffffffu, m3, o));
        }
        float x0 = act ? __expf(e0 - m0) : 0.f;
        float x1 = act ? __expf(e1 - m1) : 0.f;
        float x2 = act ? __expf(e2 - m2) : 0.f;
        float x3 = act ? __expf(e3 - m3) : 0.f;
        float d0 = x0, d1 = x1, d2 = x2, d3 = x3;
#pragma unroll
        for (int o = 16; o; o >>= 1) {
            d0 += __shfl_xor_sync(0xffffffffu, d0, o);
            d1 += __shfl_xor_sync(0xffffffffu, d1, o);
            d2 += __shfl_xor_sync(0xffffffffu, d2, o);
            d3 += __shfl_xor_sync(0xffffffffu, d3, o);
        }
        float a0 = x0 / fmaxf(d0, 1e-9f), a1 = x1 / fmaxf(d1, 1e-9f);
        float a2 = x2 / fmaxf(d2, 1e-9f), a3 = x3 / fmaxf(d3, 1e-9f);
        if (act) {
            *(float4*)(&a_sm[w][lane * 4]) = make_float4(a0, a1, a2, a3);
            s_sm[w][lane] = se.x;
            if (aout)
                *(float4*)(aout + (size_t)se.y * HH) = make_float4(a0, a1, a2, a3);
        }
        __syncwarp();
        gather_chunk(s_sm[w], a_sm[w], deg, half, hd, c0, acc);
        __syncwarp();
    } else {
        // ===== general path (deg > 32): 3-phase with register cache =====
        float m0 = -1e30f, m1 = -1e30f, m2 = -1e30f, m3 = -1e30f;
        float ec0[2], ec1[2], ec2[2], ec3[2];
        for (int i = lane, r = 0; i < deg; i += 32, ++r) {
            int s = g_cse[base + i].x;
            float4 el4 = *(const float4*)(g_el + (size_t)s * HH);
            float e0 = lrelu(el4.x + er4.x);
            float e1 = lrelu(el4.y + er4.y);
            float e2 = lrelu(el4.z + er4.z);
            float e3 = lrelu(el4.w + er4.w);
            if (r < 2) { ec0[r] = e0; ec1[r] = e1; ec2[r] = e2; ec3[r] = e3; }
            m0 = fmaxf(m0, e0); m1 = fmaxf(m1, e1); m2 = fmaxf(m2, e2); m3 = fmaxf(m3, e3);
        }
#pragma unroll
        for (int o = 16; o; o >>= 1) {
            m0 = fmaxf(m0, __shfl_xor_sync(0xffffffffu, m0, o));
            m1 = fmaxf(m1, __shfl_xor_sync(0xffffffffu, m1, o));
            m2 = fmaxf(m2, __shfl_xor_sync(0xffffffffu, m2, o));
            m3 = fmaxf(m3, __shfl_xor_sync(0xffffffffu, m3, o));
        }
        float d0 = 0.f, d1 = 0.f, d2 = 0.f, d3 = 0.f;
        for (int i = lane, r = 0; i < deg; i += 32, ++r) {
            float e0, e1, e2, e3;
            if (r < 2) { e0 = ec0[r]; e1 = ec1[r]; e2 = ec2[r]; e3 = ec3[r]; }
            else {
                int s = g_cse[base + i].x;
                float4 el4 = *(const float4*)(g_el + (size_t)s * HH);
                e0 = lrelu(el4.x + er4.x); e1 = lrelu(el4.y + er4.y);
                e2 = lrelu(el4.z + er4.z); e3 = lrelu(el4.w + er4.w);
            }
            float x0 = __expf(e0 - m0), x1 = __expf(e1 - m1);
            float x2 = __expf(e2 - m2), x3 = __expf(e3 - m3);
            if (r < 2) { ec0[r] = x0; ec1[r] = x1; ec2[r] = x2; ec3[r] = x3; }
            d0 += x0; d1 += x1; d2 += x2; d3 += x3;
        }
#pragma unroll
        for (int o = 16; o; o >>= 1) {
            d0 += __shfl_xor_sync(0xffffffffu, d0, o);
            d1 += __shfl_xor_sync(0xffffffffu, d1, o);
            d2 += __shfl_xor_sync(0xffffffffu, d2, o);
            d3 += __shfl_xor_sync(0xffffffffu, d3, o);
        }
        float i0 = 1.f / fmaxf(d0, 1e-9f), i1 = 1.f / fmaxf(d1, 1e-9f);
        float i2 = 1.f / fmaxf(d2, 1e-9f), i3 = 1.f / fmaxf(d3, 1e-9f);

        for (int j0 = 0; j0 < deg; j0 += 32) {
            int i = j0 + lane, r = i >> 5;
            if (i < deg) {
                int2 se = g_cse[base + i];
                float x0, x1, x2, x3;
                if (r < 2) { x0 = ec0[r]; x1 = ec1[r]; x2 = ec2[r]; x3 = ec3[r]; }
                else {
                    float4 el4 = *(const float4*)(g_el + (size_t)se.x * HH);
                    x0 = __expf(lrelu(el4.x + er4.x) - m0);
                    x1 = __expf(lrelu(el4.y + er4.y) - m1);
                    x2 = __expf(lrelu(el4.z + er4.z) - m2);
                    x3 = __expf(lrelu(el4.w + er4.w) - m3);
                }
                float a0 = x0 * i0, a1 = x1 * i1, a2 = x2 * i2, a3 = x3 * i3;
                *(float4*)(&a_sm[w][lane * 4]) = make_float4(a0, a1, a2, a3);
                s_sm[w][lane] = se.x;
                if (aout)
                    *(float4*)(aout + (size_t)se.y * HH) = make_float4(a0, a1, a2, a3);
            }
            __syncwarp();
            int cnt = min(32, deg - j0);
            gather_chunk(s_sm[w], a_sm[w], cnt, half, hd, c0, acc);
            __syncwarp();
        }
    }

    // ---- merge even/odd edge partials across half-warps ----
#pragma unroll
    for (int k = 0; k < 8; k++)
        acc[k] += __shfl_xor_sync(0xffffffffu, acc[k], 16);

    // ---- epilogue: residual + bias + ELU (lanes 0-15, 8 cols each) ----
    if (lane < 16) {
        float xv[8];
        if (XIN_H) {
            uint4 qx = *(const uint4*)((const __half*)xin_ + (size_t)n * FF + c0);
            float2 f;
            f = h2f(qx.x); xv[0] = f.x; xv[1] = f.y;
            f = h2f(qx.y); xv[2] = f.x; xv[3] = f.y;
            f = h2f(qx.z); xv[4] = f.x; xv[5] = f.y;
            f = h2f(qx.w); xv[6] = f.x; xv[7] = f.y;
        } else {
            float4 a0 = *(const float4*)((const float*)xin_ + (size_t)n * FF + c0);
            float4 a1 = *(const float4*)((const float*)xin_ + (size_t)n * FF + c0 + 4);
            xv[0] = a0.x; xv[1] = a0.y; xv[2] = a0.z; xv[3] = a0.w;
            xv[4] = a1.x; xv[5] = a1.y; xv[6] = a1.z; xv[7] = a1.w;
        }
        float4 bv0 = *(const float4*)(bias + c0);
        float4 bv1 = *(const float4*)(bias + c0 + 4);
        float bb[8] = { bv0.x, bv0.y, bv0.z, bv0.w, bv1.x, bv1.y, bv1.z, bv1.w };
        float rr[8];
#pragma unroll
        for (int k = 0; k < 8; k++) {
            float v = acc[k] + xv[k] + bb[k];
            rr[k] = v > 0.f ? v : (__expf(v) - 1.f);
        }
        if (XOUT_H) {
            uint4 o;
            __half2 p;
            p = __floats2half2_rn(rr[0], rr[1]); o.x = *(uint32_t*)&p;
            p = __floats2half2_rn(rr[2], rr[3]); o.y = *(uint32_t*)&p;
            p = __floats2half2_rn(rr[4], rr[5]); o.z = *(uint32_t*)&p;
            p = __floats2half2_rn(rr[6], rr[7]); o.w = *(uint32_t*)&p;
            *(uint4*)((__half*)xout_ + (size_t)n * FF + c0) = o;
        } else {
            *(float4*)((float*)xout_ + (size_t)n * FF + c0)
                = make_float4(rr[0], rr[1], rr[2], rr[3]);
            *(float4*)((float*)xout_ + (size_t)n * FF + c0 + 4)
                = make_float4(rr[4], rr[5], rr[6], rr[7]);
        }
    }
}

// ---------------- launch ----------------
extern "C" void kernel_launch(void* const* d_in, const int* in_sizes, int n_in,
                              void* d_out, int out_size) {
    const float* h     = (const float*)d_in[0];
    const int*   src   = (const int*)d_in[1];
    const int*   dst   = (const int*)d_in[2];
    const float* Ws    = (const float*)d_in[3];
    const float* attnl = (const float*)d_in[4];
    const float* attnr = (const float*)d_in[5];
    const float* bias  = (const float*)d_in[6];

    float* out_x = (float*)d_out;
    float* out_a = out_x + ((size_t)out_size - (size_t)EE * HH);

    const int gemm_smem = 1024 + 2 * (128 * SA_STRIDE * 2);  // 70656B
    cudaFuncSetAttribute(k_gemm<false>, cudaFuncAttributeMaxDynamicSharedMemorySize, gemm_smem);
    cudaFuncSetAttribute(k_gemm<true>,  cudaFuncAttributeMaxDynamicSharedMemorySize, gemm_smem);

    __half *p_xha, *p_xhb, *p_wh;
    cudaGetSymbolAddress((void**)&p_xha, g_xha);
    cudaGetSymbolAddress((void**)&p_xhb, g_xhb);
    cudaGetSymbolAddress((void**)&p_wh, g_wh);

    // Launch order keeps layer-0 k_gemm at index 3 (the profiled slot).
    k_prep<<<(NN + 255) / 256, 256>>>(Ws);       // W fp16 + zero deg/fill
    k_hist<<<(EE + 255) / 256, 256>>>(dst);
    int nb = (NN + 511) / 512;
    k_scan1<<<nb, 512>>>();
    k_gemm<false><<<GTILES, 256, gemm_smem>>>(h, p_wh, attnl, attnr);   // layer 0
    k_scan2<<<1, 256>>>(nb);
    k_scatter<<<(EE + 255) / 256, 256>>>(src, dst);

    int eblk = (NN + 7) / 8;
    // layer 0: xin = h (fp32), xout = g_xha (fp16)
    k_edge<false, true><<<eblk, 256>>>(h, bias, p_xha, nullptr);
    // layer 1
    k_gemm<true><<<GTILES, 256, gemm_smem>>>(p_xha, p_wh + (size_t)1 * FF * FF,
                                             attnl + 1 * HH * DD, attnr + 1 * HH * DD);
    k_edge<true, true><<<eblk, 256>>>(p_xha, bias + 1 * HH * DD, p_xhb, nullptr);
    // layer 2
    k_gemm<true><<<GTILES, 256, gemm_smem>>>(p_xhb, p_wh + (size_t)2 * FF * FF,
                                             attnl + 2 * HH * DD, attnr + 2 * HH * DD);
    k_edge<true, false><<<eblk, 256>>>(p_xhb, bias + 2 * HH * DD, out_x, out_a);

    (void)in_sizes; (void)n_in;
}